// round 2
// baseline (speedup 1.0000x reference)
#include <cuda_runtime.h>
#include <cstdint>

// Partial label counts per block: [c0, c2]. Deterministic: every slot is
// overwritten on every launch, so graph replays are safe without a zeroing pass.
#define COUNT_BLOCKS 256
#define COUNT_THREADS 256

__device__ int g_partial_c0[COUNT_BLOCKS];
__device__ int g_partial_c2[COUNT_BLOCKS];

// labels are int32 (jax demotes int64 -> int32 with default x64-disabled config;
// harness delivers int32 per metadata).
__global__ void count_labels_kernel(const int* __restrict__ labels, int n) {
    int stride = gridDim.x * blockDim.x;
    int c0 = 0, c2 = 0;
    for (int i = blockIdx.x * blockDim.x + threadIdx.x; i < n; i += stride) {
        int l = labels[i];
        c0 += (l == 0);
        c2 += (l == 2);
    }
    #pragma unroll
    for (int off = 16; off > 0; off >>= 1) {
        c0 += __shfl_down_sync(0xffffffffu, c0, off);
        c2 += __shfl_down_sync(0xffffffffu, c2, off);
    }
    __shared__ int s0[COUNT_THREADS / 32];
    __shared__ int s2[COUNT_THREADS / 32];
    int wid = threadIdx.x >> 5;
    int lane = threadIdx.x & 31;
    if (lane == 0) { s0[wid] = c0; s2[wid] = c2; }
    __syncthreads();
    if (threadIdx.x == 0) {
        int t0 = 0, t2 = 0;
        #pragma unroll
        for (int w = 0; w < COUNT_THREADS / 32; ++w) { t0 += s0[w]; t2 += s2[w]; }
        g_partial_c0[blockIdx.x] = t0;
        g_partial_c2[blockIdx.x] = t2;
    }
}

// Single block: warps 0..2 compute cos(tensor_1[j], tensor_2[j]) for j=warp id;
// warp 3 sums the partial counts; thread 0 combines and writes the scalar.
__global__ void finish_kernel(const float* __restrict__ t1,
                              const float* __restrict__ t2,
                              int n, int d,
                              float* __restrict__ out) {
    __shared__ float s_cos[3];
    __shared__ int s_c0, s_c2;

    int wid = threadIdx.x >> 5;
    int lane = threadIdx.x & 31;

    if (wid < 3) {
        const float* a = t1 + (size_t)wid * d;
        const float* b = t2 + (size_t)wid * d;
        float dot = 0.f, na = 0.f, nb = 0.f;
        for (int i = lane; i < d; i += 32) {
            float x = a[i], y = b[i];
            dot += x * y;
            na  += x * x;
            nb  += y * y;
        }
        #pragma unroll
        for (int off = 16; off > 0; off >>= 1) {
            dot += __shfl_down_sync(0xffffffffu, dot, off);
            na  += __shfl_down_sync(0xffffffffu, na, off);
            nb  += __shfl_down_sync(0xffffffffu, nb, off);
        }
        if (lane == 0) {
            float denom = sqrtf(na) * sqrtf(nb);
            denom = fmaxf(denom, 1e-8f);
            s_cos[wid] = dot / denom;
        }
    } else if (wid == 3) {
        int c0 = 0, c2 = 0;
        for (int i = lane; i < COUNT_BLOCKS; i += 32) {
            c0 += g_partial_c0[i];
            c2 += g_partial_c2[i];
        }
        #pragma unroll
        for (int off = 16; off > 0; off >>= 1) {
            c0 += __shfl_down_sync(0xffffffffu, c0, off);
            c2 += __shfl_down_sync(0xffffffffu, c2, off);
        }
        if (lane == 0) { s_c0 = c0; s_c2 = c2; }
    }
    __syncthreads();

    if (threadIdx.x == 0) {
        int c0 = s_c0, c2 = s_c2;
        int c1 = n - c0 - c2;
        float cos0 = s_cos[0], cos1 = s_cos[1], cos2 = s_cos[2];
        float total = (float)c0 * (1.0f - cos0)
                    + (float)c2 * (1.0f - cos2)
                    + (float)c1 * fabsf(cos1);
        out[0] = total / (float)n;
    }
}

extern "C" void kernel_launch(void* const* d_in, const int* in_sizes, int n_in,
                              void* d_out, int out_size) {
    const float* t1 = (const float*)d_in[0];
    const float* t2 = (const float*)d_in[1];
    const int* labels = (const int*)d_in[2];
    float* out = (float*)d_out;

    int n = in_sizes[2];              // 65536 labels
    int d = in_sizes[0] / n;          // 512

    count_labels_kernel<<<COUNT_BLOCKS, COUNT_THREADS>>>(labels, n);
    finish_kernel<<<1, 128>>>(t1, t2, n, d, out);
}

// round 3
// speedup vs baseline: 1.0295x; 1.0295x over previous
#include <cuda_runtime.h>
#include <cstdint>

#define CNT_BLOCKS 64
#define NTHR 256

// Zero-initialized at module load; the finalizing block resets them at the end
// of every launch, so graph replays always start from zero. Deterministic.
__device__ int g_c0 = 0;
__device__ int g_c2 = 0;
__device__ unsigned g_done = 0;
__device__ float g_cos[3];

__global__ void fused_kernel(const float* __restrict__ t1,
                             const float* __restrict__ t2,
                             const int* __restrict__ labels,
                             int n, int d,
                             float* __restrict__ out) {
    const int nb = gridDim.x;                 // CNT_BLOCKS + 1
    const bool cos_block = (blockIdx.x == nb - 1);
    const int wid = threadIdx.x >> 5;
    const int lane = threadIdx.x & 31;

    if (cos_block) {
        // Warps 0..2: cosine of rows 0..2 (labels are in {0,1,2}, and the
        // reference gathers rows by LABEL VALUE, so only rows 0..2 matter).
        if (wid < 3) {
            const float4* a = (const float4*)(t1 + (size_t)wid * d);
            const float4* b = (const float4*)(t2 + (size_t)wid * d);
            const int d4 = d >> 2;
            float dot = 0.f, na = 0.f, nbb = 0.f;
            for (int i = lane; i < d4; i += 32) {
                float4 x = a[i], y = b[i];
                dot += x.x * y.x + x.y * y.y + x.z * y.z + x.w * y.w;
                na  += x.x * x.x + x.y * x.y + x.z * x.z + x.w * x.w;
                nbb += y.x * y.x + y.y * y.y + y.z * y.z + y.w * y.w;
            }
            #pragma unroll
            for (int off = 16; off > 0; off >>= 1) {
                dot += __shfl_down_sync(0xffffffffu, dot, off);
                na  += __shfl_down_sync(0xffffffffu, na, off);
                nbb += __shfl_down_sync(0xffffffffu, nbb, off);
            }
            if (lane == 0) {
                float denom = fmaxf(sqrtf(na) * sqrtf(nbb), 1e-8f);
                g_cos[wid] = dot / denom;
            }
        }
    } else {
        // Counting blocks: each thread loads one int4 of labels (one wave for
        // n = 65536 with 64 blocks x 256 threads), plus a generic tail.
        const int n4 = n >> 2;
        const int stride = (nb - 1) * NTHR;
        int c0 = 0, c2 = 0;
        const int4* l4 = (const int4*)labels;
        for (int i = blockIdx.x * NTHR + threadIdx.x; i < n4; i += stride) {
            int4 v = l4[i];
            c0 += (v.x == 0) + (v.y == 0) + (v.z == 0) + (v.w == 0);
            c2 += (v.x == 2) + (v.y == 2) + (v.z == 2) + (v.w == 2);
        }
        if (blockIdx.x == 0) {  // tail (n not divisible by 4)
            for (int i = (n4 << 2) + threadIdx.x; i < n; i += NTHR) {
                int l = labels[i];
                c0 += (l == 0);
                c2 += (l == 2);
            }
        }
        #pragma unroll
        for (int off = 16; off > 0; off >>= 1) {
            c0 += __shfl_down_sync(0xffffffffu, c0, off);
            c2 += __shfl_down_sync(0xffffffffu, c2, off);
        }
        __shared__ int s0[NTHR / 32];
        __shared__ int s2[NTHR / 32];
        if (lane == 0) { s0[wid] = c0; s2[wid] = c2; }
        __syncthreads();
        if (threadIdx.x == 0) {
            int t0 = 0, t2v = 0;
            #pragma unroll
            for (int w = 0; w < NTHR / 32; ++w) { t0 += s0[w]; t2v += s2[w]; }
            atomicAdd(&g_c0, t0);
            atomicAdd(&g_c2, t2v);
        }
    }

    // Make this block's writes globally visible, then take a ticket.
    __threadfence();
    __syncthreads();
    if (threadIdx.x == 0) {
        unsigned ticket = atomicAdd(&g_done, 1u);
        if (ticket == (unsigned)(nb - 1)) {
            // Last block to finish: everything is visible now.
            int c0 = *(volatile int*)&g_c0;
            int c2 = *(volatile int*)&g_c2;
            float cos0 = *(volatile float*)&g_cos[0];
            float cos1 = *(volatile float*)&g_cos[1];
            float cos2 = *(volatile float*)&g_cos[2];
            int c1 = n - c0 - c2;
            float total = (float)c0 * (1.0f - cos0)
                        + (float)c2 * (1.0f - cos2)
                        + (float)c1 * fabsf(cos1);
            out[0] = total / (float)n;
            // Reset for the next graph replay.
            *(volatile int*)&g_c0 = 0;
            *(volatile int*)&g_c2 = 0;
            __threadfence();
            *(volatile unsigned*)&g_done = 0;
            __threadfence();
        }
    }
}

extern "C" void kernel_launch(void* const* d_in, const int* in_sizes, int n_in,
                              void* d_out, int out_size) {
    const float* t1 = (const float*)d_in[0];
    const float* t2 = (const float*)d_in[1];
    const int* labels = (const int*)d_in[2];
    float* out = (float*)d_out;

    int n = in_sizes[2];          // 65536 labels
    int d = in_sizes[0] / n;      // 512

    fused_kernel<<<CNT_BLOCKS + 1, NTHR>>>(t1, t2, labels, n, d, out);
}